// round 4
// baseline (speedup 1.0000x reference)
#include <cuda_runtime.h>
#include <cstdint>

// ---------------------------------------------------------------------------
// SDPQuantizer: global min/max -> int8 quantize -> split high/low nibble ->
// per-8-group top-4 mask on low nibble -> dequantize.
// x: (8, 4096, 2048) fp32, 67,108,864 elements (256 MB). Output fp32.
//
// L2-reuse scheme: the min/max pass uses CACHING loads so the ~126MB L2
// retains the most-recently-read TAIL of x. The quantize pass then walks x
// in REVERSE block order, consuming those hot lines first (before its own
// streaming stores evict them). Quant loads use ld.global.cg, stores stcs.
// ---------------------------------------------------------------------------

__device__ unsigned int g_min_enc = 0x80000000u;  // enc(0.0f)
__device__ unsigned int g_max_enc = 0x80000000u;

__device__ __forceinline__ unsigned int enc_f(float f) {
    unsigned int u = __float_as_uint(f);
    return (u & 0x80000000u) ? ~u : (u | 0x80000000u);
}
__device__ __forceinline__ float dec_f(unsigned int u) {
    return (u & 0x80000000u) ? __uint_as_float(u & 0x7FFFFFFFu)
                             : __uint_as_float(~u);
}

__device__ __forceinline__ float v4min(float4 v) {
    return fminf(fminf(v.x, v.y), fminf(v.z, v.w));
}
__device__ __forceinline__ float v4max(float4 v) {
    return fmaxf(fmaxf(v.x, v.y), fmaxf(v.z, v.w));
}

// One thread = 8 contiguous float4 loads (32 elements), CACHING loads so the
// tail of x stays resident in L2 for the quant pass. Exact-coverage grid.
__global__ void sdp_minmax_kernel(const float4* __restrict__ x) {
    const size_t base = ((size_t)blockIdx.x * blockDim.x + threadIdx.x) * 8;

    float lmin = 0.0f, lmax = 0.0f;
    #pragma unroll
    for (int k = 0; k < 8; k++) {
        float4 v = x[base + k];          // default caching load (L1+L2)
        lmin = fminf(lmin, v4min(v));
        lmax = fmaxf(lmax, v4max(v));
    }

    #pragma unroll
    for (int o = 16; o > 0; o >>= 1) {
        lmin = fminf(lmin, __shfl_xor_sync(0xFFFFFFFFu, lmin, o));
        lmax = fmaxf(lmax, __shfl_xor_sync(0xFFFFFFFFu, lmax, o));
    }
    __shared__ float smin[8], smax[8];
    const int lane = threadIdx.x & 31;
    const int warp = threadIdx.x >> 5;
    if (lane == 0) { smin[warp] = lmin; smax[warp] = lmax; }
    __syncthreads();
    if (warp == 0) {
        const int nw = blockDim.x >> 5;
        lmin = (lane < nw) ? smin[lane] : 0.0f;
        lmax = (lane < nw) ? smax[lane] : 0.0f;
        #pragma unroll
        for (int o = 4; o > 0; o >>= 1) {
            lmin = fminf(lmin, __shfl_xor_sync(0xFFFFFFFFu, lmin, o));
            lmax = fmaxf(lmax, __shfl_xor_sync(0xFFFFFFFFu, lmax, o));
        }
        if (lane == 0) {
            atomicMin(&g_min_enc, enc_f(lmin));
            atomicMax(&g_max_enc, enc_f(lmax));
        }
    }
}

// compare-exchange: u becomes max, v becomes min
#define SDP_CE(u, v) { float _hi = fmaxf(u, v), _lo = fminf(u, v); u = _hi; v = _lo; }

__device__ __forceinline__ void sdp_process_group(
    float4 va, float4 vb, float scale, float inv_scale,
    float4& oa, float4& ob)
{
    float xv[8]  = {va.x, va.y, va.z, va.w, vb.x, vb.y, vb.z, vb.w};
    float q[8];
    float mag[8];

    #pragma unroll
    for (int i = 0; i < 8; i++) {
        // Fast path: multiply by correctly-rounded reciprocal; the product
        // differs from the exact quotient by <=~1.5 ulp, which can only flip
        // round-half-to-even essentially on a .5 tie: detect that
        // neighborhood and redo with exact IEEE division (rare, ~0.2%).
        float y = xv[i] * inv_scale;
        float r = rintf(y);
        if (fabsf(fabsf(y - r) - 0.5f) < 1e-3f) {
            r = rintf(__fdiv_rn(xv[i], scale));
        }
        r = fminf(fmaxf(r, -128.0f), 127.0f);
        q[i]   = r;
        mag[i] = fabsf(r);   // integer-valued, 0..128
    }

    // 4th-largest of 8 via two sorted-4 runs + merge rank selection.
    float a0 = mag[0], a1 = mag[1], a2 = mag[2], a3 = mag[3];
    float b0 = mag[4], b1 = mag[5], b2 = mag[6], b3 = mag[7];
    SDP_CE(a0, a1); SDP_CE(a2, a3); SDP_CE(a0, a2); SDP_CE(a1, a3); SDP_CE(a1, a2);
    SDP_CE(b0, b1); SDP_CE(b2, b3); SDP_CE(b0, b2); SDP_CE(b1, b3); SDP_CE(b1, b2);
    float thr = fmaxf(fmaxf(a3, b3),
                      fmaxf(fminf(a0, b2), fmaxf(fminf(a1, b1), fminf(a2, b0))));

    #pragma unroll
    for (int i = 0; i < 8; i++) {
        const float tr16 = floorf(mag[i] * 0.0625f) * 16.0f;
        const float val  = (mag[i] >= thr) ? mag[i] : tr16;
        const float x_sdp = scale * copysignf(val, q[i]);
        xv[i] = xv[i] + (x_sdp - xv[i]);   // replicate reference rounding
    }

    oa = make_float4(xv[0], xv[1], xv[2], xv[3]);
    ob = make_float4(xv[4], xv[5], xv[6], xv[7]);
}

// One thread = two groups (16 elements, 4 LDG.128). REVERSED block order so
// the earliest-scheduled blocks consume the L2-resident tail of x.
__global__ void sdp_quant_kernel(const float4* __restrict__ x,
                                 float4* __restrict__ out) {
    const float r_min = dec_f(g_min_enc);
    const float r_max = dec_f(g_max_enc);
    const float scale = fmaxf(__fdiv_rn(r_max - r_min, 255.0f), 1e-8f);
    const float inv_scale = __frcp_rn(scale);

    const unsigned int chunk = gridDim.x - 1u - blockIdx.x;   // reverse order
    const size_t base = ((size_t)chunk * blockDim.x + threadIdx.x) * 4;

    float4 v0 = __ldcg(&x[base + 0]);
    float4 v1 = __ldcg(&x[base + 1]);
    float4 v2 = __ldcg(&x[base + 2]);
    float4 v3 = __ldcg(&x[base + 3]);

    float4 o0, o1, o2, o3;
    sdp_process_group(v0, v1, scale, inv_scale, o0, o1);
    sdp_process_group(v2, v3, scale, inv_scale, o2, o3);

    __stcs(&out[base + 0], o0);
    __stcs(&out[base + 1], o1);
    __stcs(&out[base + 2], o2);
    __stcs(&out[base + 3], o3);
}

extern "C" void kernel_launch(void* const* d_in, const int* in_sizes, int n_in,
                              void* d_out, int out_size) {
    const float* x = (const float*)d_in[0];
    float* out = (float*)d_out;
    const int n = in_sizes[0];          // 67,108,864

    const int threads = 256;

    const int mm_blocks = n / (threads * 32);   // 32 elements per thread
    sdp_minmax_kernel<<<mm_blocks, threads>>>((const float4*)x);

    const int q_blocks = n / (threads * 16);    // 16 elements per thread
    sdp_quant_kernel<<<q_blocks, threads>>>((const float4*)x, (float4*)out);
}

// round 5
// speedup vs baseline: 1.0757x; 1.0757x over previous
#include <cuda_runtime.h>
#include <cstdint>

// ---------------------------------------------------------------------------
// SDPQuantizer: global min/max -> int8 quantize -> split high/low nibble ->
// per-8-group top-4 mask on low nibble -> dequantize.
// x: (8, 4096, 2048) fp32, 67,108,864 elements (256 MB). Output fp32.
//
// Kernel 1: min/max. One thread = 32 contiguous elements (8 front-batched
//   LDG.128, streaming). REDUX-based warp/block reduce on monotone-encoded
//   uints, one atomicMin/Max per block. Globals statically initialized to
//   enc(0); idempotent across graph replays.
// Kernel 2: quantize (R3-proven config): one thread = 2 groups (16 elems,
//   4 LDG.128 streaming), rank-4 selection network, reciprocal-multiply with
//   rare exact-division rescue on half-integer ties.
// ---------------------------------------------------------------------------

__device__ unsigned int g_min_enc = 0x80000000u;  // enc(0.0f)
__device__ unsigned int g_max_enc = 0x80000000u;

__device__ __forceinline__ unsigned int enc_f(float f) {
    unsigned int u = __float_as_uint(f);
    return (u & 0x80000000u) ? ~u : (u | 0x80000000u);
}
__device__ __forceinline__ float dec_f(unsigned int u) {
    return (u & 0x80000000u) ? __uint_as_float(u & 0x7FFFFFFFu)
                             : __uint_as_float(~u);
}

__device__ __forceinline__ float v4min(float4 v) {
    return fminf(fminf(v.x, v.y), fminf(v.z, v.w));
}
__device__ __forceinline__ float v4max(float4 v) {
    return fmaxf(fmaxf(v.x, v.y), fmaxf(v.z, v.w));
}

// One thread = 8 contiguous float4 streaming loads (32 elements).
// Exact-coverage grid: gridDim.x*blockDim.x == n/32.
__global__ void sdp_minmax_kernel(const float4* __restrict__ x) {
    const size_t base = ((size_t)blockIdx.x * blockDim.x + threadIdx.x) * 8;

    // Front-batched independent loads for MLP=8.
    float4 v0 = __ldcs(&x[base + 0]);
    float4 v1 = __ldcs(&x[base + 1]);
    float4 v2 = __ldcs(&x[base + 2]);
    float4 v3 = __ldcs(&x[base + 3]);
    float4 v4 = __ldcs(&x[base + 4]);
    float4 v5 = __ldcs(&x[base + 5]);
    float4 v6 = __ldcs(&x[base + 6]);
    float4 v7 = __ldcs(&x[base + 7]);

    float lmin = fminf(fminf(fminf(v4min(v0), v4min(v1)), fminf(v4min(v2), v4min(v3))),
                       fminf(fminf(v4min(v4), v4min(v5)), fminf(v4min(v6), v4min(v7))));
    float lmax = fmaxf(fmaxf(fmaxf(v4max(v0), v4max(v1)), fmaxf(v4max(v2), v4max(v3))),
                       fmaxf(fmaxf(v4max(v4), v4max(v5)), fmaxf(v4max(v6), v4max(v7))));
    lmin = fminf(lmin, 0.0f);
    lmax = fmaxf(lmax, 0.0f);

    // Warp reduce via single-instruction REDUX on monotone-encoded uints.
    unsigned int emin = __reduce_min_sync(0xFFFFFFFFu, enc_f(lmin));
    unsigned int emax = __reduce_max_sync(0xFFFFFFFFu, enc_f(lmax));

    __shared__ unsigned int smin[8], smax[8];
    const int lane = threadIdx.x & 31;
    const int warp = threadIdx.x >> 5;
    if (lane == 0) { smin[warp] = emin; smax[warp] = emax; }
    __syncthreads();
    if (threadIdx.x < 8) {                       // lanes 0-7 of warp 0
        emin = __reduce_min_sync(0xFFu, smin[threadIdx.x]);
        emax = __reduce_max_sync(0xFFu, smax[threadIdx.x]);
        if (threadIdx.x == 0) {
            atomicMin(&g_min_enc, emin);
            atomicMax(&g_max_enc, emax);
        }
    }
}

// compare-exchange: u becomes max, v becomes min
#define SDP_CE(u, v) { float _hi = fmaxf(u, v), _lo = fminf(u, v); u = _hi; v = _lo; }

__device__ __forceinline__ void sdp_process_group(
    float4 va, float4 vb, float scale, float inv_scale,
    float4& oa, float4& ob)
{
    float xv[8]  = {va.x, va.y, va.z, va.w, vb.x, vb.y, vb.z, vb.w};
    float q[8];
    float mag[8];

    #pragma unroll
    for (int i = 0; i < 8; i++) {
        // Fast path: multiply by correctly-rounded reciprocal; differs from
        // the exact quotient by <=~1.5 ulp, which can only flip
        // round-half-to-even essentially on a .5 tie: detect that
        // neighborhood and redo with exact IEEE division (rare, ~0.2%).
        float y = xv[i] * inv_scale;
        float r = rintf(y);
        if (fabsf(fabsf(y - r) - 0.5f) < 1e-3f) {
            r = rintf(__fdiv_rn(xv[i], scale));
        }
        r = fminf(fmaxf(r, -128.0f), 127.0f);
        q[i]   = r;
        mag[i] = fabsf(r);   // integer-valued, 0..128
    }

    // 4th-largest of 8 via two sorted-4 runs + merge rank selection.
    float a0 = mag[0], a1 = mag[1], a2 = mag[2], a3 = mag[3];
    float b0 = mag[4], b1 = mag[5], b2 = mag[6], b3 = mag[7];
    SDP_CE(a0, a1); SDP_CE(a2, a3); SDP_CE(a0, a2); SDP_CE(a1, a3); SDP_CE(a1, a2);
    SDP_CE(b0, b1); SDP_CE(b2, b3); SDP_CE(b0, b2); SDP_CE(b1, b3); SDP_CE(b1, b2);
    float thr = fmaxf(fmaxf(a3, b3),
                      fmaxf(fminf(a0, b2), fmaxf(fminf(a1, b1), fminf(a2, b0))));

    #pragma unroll
    for (int i = 0; i < 8; i++) {
        const float tr16 = floorf(mag[i] * 0.0625f) * 16.0f;
        const float val  = (mag[i] >= thr) ? mag[i] : tr16;
        const float x_sdp = scale * copysignf(val, q[i]);
        xv[i] = xv[i] + (x_sdp - xv[i]);   // replicate reference rounding
    }

    oa = make_float4(xv[0], xv[1], xv[2], xv[3]);
    ob = make_float4(xv[4], xv[5], xv[6], xv[7]);
}

// One thread = two groups (16 elements, 4 LDG.128). Forward order, exact
// coverage grid. (R3-proven: 5.96 TB/s.)
__global__ void sdp_quant_kernel(const float4* __restrict__ x,
                                 float4* __restrict__ out) {
    const float r_min = dec_f(g_min_enc);
    const float r_max = dec_f(g_max_enc);
    const float scale = fmaxf(__fdiv_rn(r_max - r_min, 255.0f), 1e-8f);
    const float inv_scale = __frcp_rn(scale);

    const size_t base = ((size_t)blockIdx.x * blockDim.x + threadIdx.x) * 4;
    float4 v0 = __ldcs(&x[base + 0]);
    float4 v1 = __ldcs(&x[base + 1]);
    float4 v2 = __ldcs(&x[base + 2]);
    float4 v3 = __ldcs(&x[base + 3]);

    float4 o0, o1, o2, o3;
    sdp_process_group(v0, v1, scale, inv_scale, o0, o1);
    sdp_process_group(v2, v3, scale, inv_scale, o2, o3);

    __stcs(&out[base + 0], o0);
    __stcs(&out[base + 1], o1);
    __stcs(&out[base + 2], o2);
    __stcs(&out[base + 3], o3);
}

extern "C" void kernel_launch(void* const* d_in, const int* in_sizes, int n_in,
                              void* d_out, int out_size) {
    const float* x = (const float*)d_in[0];
    float* out = (float*)d_out;
    const int n = in_sizes[0];          // 67,108,864

    const int threads = 256;

    const int mm_blocks = n / (threads * 32);   // 32 elements per thread
    sdp_minmax_kernel<<<mm_blocks, threads>>>((const float4*)x);

    const int q_blocks = n / (threads * 16);    // 16 elements per thread
    sdp_quant_kernel<<<q_blocks, threads>>>((const float4*)x, (float4*)out);
}

// round 6
// speedup vs baseline: 1.1481x; 1.0673x over previous
#include <cuda_runtime.h>
#include <cstdint>

// ---------------------------------------------------------------------------
// SDPQuantizer: global min/max -> int8 quantize -> split high/low nibble ->
// per-8-group top-4 mask on low nibble -> dequantize.
// x: (8, 4096, 2048) fp32, 67,108,864 elements (256 MB). Output fp32.
//
// Kernel 1: min/max. One thread = 8 contiguous elements (2 LDG.128,
//   streaming) -- low MLP_p1 to stay on the cross-CTA L1tex spread floor.
//   REDUX warp/block reduce on monotone-encoded uints, one atomic per block.
//   Globals statically initialized to enc(0); idempotent across replays.
// Kernel 2: quantize. One thread = 2 groups (16 elems, 4 LDG.128 streaming;
//   R3-proven 5.96 TB/s pattern), rank-4 selection network, signed-trunc
//   epilogue, reciprocal-multiply with rare exact-division tie rescue.
// ---------------------------------------------------------------------------

__device__ unsigned int g_min_enc = 0x80000000u;  // enc(0.0f)
__device__ unsigned int g_max_enc = 0x80000000u;

__device__ __forceinline__ unsigned int enc_f(float f) {
    unsigned int u = __float_as_uint(f);
    return (u & 0x80000000u) ? ~u : (u | 0x80000000u);
}
__device__ __forceinline__ float dec_f(unsigned int u) {
    return (u & 0x80000000u) ? __uint_as_float(u & 0x7FFFFFFFu)
                             : __uint_as_float(~u);
}

__device__ __forceinline__ float v4min(float4 v) {
    return fminf(fminf(v.x, v.y), fminf(v.z, v.w));
}
__device__ __forceinline__ float v4max(float4 v) {
    return fmaxf(fmaxf(v.x, v.y), fmaxf(v.z, v.w));
}

// One thread = 2 contiguous float4 streaming loads (8 elements).
// Exact-coverage grid: gridDim.x*blockDim.x == n/8.
__global__ void sdp_minmax_kernel(const float4* __restrict__ x) {
    const size_t base = ((size_t)blockIdx.x * blockDim.x + threadIdx.x) * 2;

    float4 v0 = __ldcs(&x[base + 0]);
    float4 v1 = __ldcs(&x[base + 1]);

    float lmin = fminf(fminf(v4min(v0), v4min(v1)), 0.0f);
    float lmax = fmaxf(fmaxf(v4max(v0), v4max(v1)), 0.0f);

    // Warp reduce via single-instruction REDUX on monotone-encoded uints.
    unsigned int emin = __reduce_min_sync(0xFFFFFFFFu, enc_f(lmin));
    unsigned int emax = __reduce_max_sync(0xFFFFFFFFu, enc_f(lmax));

    __shared__ unsigned int smin[8], smax[8];
    const int lane = threadIdx.x & 31;
    const int warp = threadIdx.x >> 5;
    if (lane == 0) { smin[warp] = emin; smax[warp] = emax; }
    __syncthreads();
    if (threadIdx.x < 8) {                       // lanes 0-7 of warp 0
        emin = __reduce_min_sync(0xFFu, smin[threadIdx.x]);
        emax = __reduce_max_sync(0xFFu, smax[threadIdx.x]);
        if (threadIdx.x == 0) {
            atomicMin(&g_min_enc, emin);
            atomicMax(&g_max_enc, emax);
        }
    }
}

// compare-exchange: u becomes max, v becomes min
#define SDP_CE(u, v) { float _hi = fmaxf(u, v), _lo = fminf(u, v); u = _hi; v = _lo; }

__device__ __forceinline__ void sdp_process_group(
    float4 va, float4 vb, float scale, float inv_scale,
    float4& oa, float4& ob)
{
    float xv[8]  = {va.x, va.y, va.z, va.w, vb.x, vb.y, vb.z, vb.w};
    float q[8];    // clipped, rounded x_int (signed, integer-valued)
    float mag[8];

    #pragma unroll
    for (int i = 0; i < 8; i++) {
        // Fast path: multiply by correctly-rounded reciprocal; differs from
        // the exact quotient by <=~1.5 ulp, which can only flip
        // round-half-to-even essentially on a .5 tie: detect that
        // neighborhood and redo with exact IEEE division (rare, ~0.2%).
        float y = xv[i] * inv_scale;
        float r = rintf(y);
        if (fabsf(fabsf(y - r) - 0.5f) < 1e-3f) {
            r = rintf(__fdiv_rn(xv[i], scale));
        }
        r = fminf(fmaxf(r, -128.0f), 127.0f);
        q[i]   = r;
        mag[i] = fabsf(r);   // integer-valued, 0..128
    }

    // 4th-largest of 8 via two sorted-4 runs + merge rank selection.
    float a0 = mag[0], a1 = mag[1], a2 = mag[2], a3 = mag[3];
    float b0 = mag[4], b1 = mag[5], b2 = mag[6], b3 = mag[7];
    SDP_CE(a0, a1); SDP_CE(a2, a3); SDP_CE(a0, a2); SDP_CE(a1, a3); SDP_CE(a1, a2);
    SDP_CE(b0, b1); SDP_CE(b2, b3); SDP_CE(b0, b2); SDP_CE(b1, b3); SDP_CE(b1, b2);
    float thr = fmaxf(fmaxf(a3, b3),
                      fmaxf(fminf(a0, b2), fmaxf(fminf(a1, b1), fminf(a2, b0))));

    #pragma unroll
    for (int i = 0; i < 8; i++) {
        // Signed truncation-to-multiple-of-16: for integer-valued q,
        // trunc(q/16)*16 == sign(q) * floor(|q|/16)*16 (exact).
        const float tr16 = truncf(q[i] * 0.0625f) * 16.0f;
        const float vs   = (mag[i] >= thr) ? q[i] : tr16;
        xv[i] = scale * vs;   // x_sdp (x + (x_sdp - x) == x_sdp to <=1 ulp)
    }

    oa = make_float4(xv[0], xv[1], xv[2], xv[3]);
    ob = make_float4(xv[4], xv[5], xv[6], xv[7]);
}

// One thread = two groups (16 elements, 4 LDG.128). Forward order, exact
// coverage grid. (R3-proven access pattern: 5.96 TB/s.)
__global__ void sdp_quant_kernel(const float4* __restrict__ x,
                                 float4* __restrict__ out) {
    const float r_min = dec_f(g_min_enc);
    const float r_max = dec_f(g_max_enc);
    const float scale = fmaxf(__fdiv_rn(r_max - r_min, 255.0f), 1e-8f);
    const float inv_scale = __frcp_rn(scale);

    const size_t base = ((size_t)blockIdx.x * blockDim.x + threadIdx.x) * 4;
    float4 v0 = __ldcs(&x[base + 0]);
    float4 v1 = __ldcs(&x[base + 1]);
    float4 v2 = __ldcs(&x[base + 2]);
    float4 v3 = __ldcs(&x[base + 3]);

    float4 o0, o1, o2, o3;
    sdp_process_group(v0, v1, scale, inv_scale, o0, o1);
    sdp_process_group(v2, v3, scale, inv_scale, o2, o3);

    __stcs(&out[base + 0], o0);
    __stcs(&out[base + 1], o1);
    __stcs(&out[base + 2], o2);
    __stcs(&out[base + 3], o3);
}

extern "C" void kernel_launch(void* const* d_in, const int* in_sizes, int n_in,
                              void* d_out, int out_size) {
    const float* x = (const float*)d_in[0];
    float* out = (float*)d_out;
    const int n = in_sizes[0];          // 67,108,864

    const int threads = 256;

    const int mm_blocks = n / (threads * 8);    // 8 elements per thread
    sdp_minmax_kernel<<<mm_blocks, threads>>>((const float4*)x);

    const int q_blocks = n / (threads * 16);    // 16 elements per thread
    sdp_quant_kernel<<<q_blocks, threads>>>((const float4*)x, (float4*)out);
}

// round 7
// speedup vs baseline: 1.1628x; 1.0127x over previous
#include <cuda_runtime.h>
#include <cstdint>

// ---------------------------------------------------------------------------
// SDPQuantizer: global min/max -> int8 quantize -> split high/low nibble ->
// per-8-group top-4 mask on low nibble -> dequantize.
// x: (8, 4096, 2048) fp32, 67,108,864 elements (256 MB). Output fp32.
//
// Kernel 1: min/max. One thread = 16 contiguous elements (4 LDG.128) with
//   L2-allocating loads (__ldcg), REVERSE chunk order: last waves read the
//   HEAD of x, leaving it resident in the ~126MB L2 for kernel 2.
// Kernel 2: quantize, R3-proven verbatim (forward order, 4 LDG.128/thread,
//   40-reg epilogue, 85.9us / 5.96 TB/s). Its first waves consume the
//   L2-resident head of x.
// ---------------------------------------------------------------------------

__device__ unsigned int g_min_enc = 0x80000000u;  // enc(0.0f)
__device__ unsigned int g_max_enc = 0x80000000u;

__device__ __forceinline__ unsigned int enc_f(float f) {
    unsigned int u = __float_as_uint(f);
    return (u & 0x80000000u) ? ~u : (u | 0x80000000u);
}
__device__ __forceinline__ float dec_f(unsigned int u) {
    return (u & 0x80000000u) ? __uint_as_float(u & 0x7FFFFFFFu)
                             : __uint_as_float(~u);
}

__device__ __forceinline__ float v4min(float4 v) {
    return fminf(fminf(v.x, v.y), fminf(v.z, v.w));
}
__device__ __forceinline__ float v4max(float4 v) {
    return fmaxf(fmaxf(v.x, v.y), fmaxf(v.z, v.w));
}

// One thread = 4 contiguous float4 loads (16 elements), L2-allocating,
// REVERSED block order. Exact coverage: gridDim.x*blockDim.x == n/16.
__global__ void sdp_minmax_kernel(const float4* __restrict__ x) {
    const unsigned int chunk = gridDim.x - 1u - blockIdx.x;   // reverse order
    const size_t base = ((size_t)chunk * blockDim.x + threadIdx.x) * 4;

    float4 v0 = __ldcg(&x[base + 0]);
    float4 v1 = __ldcg(&x[base + 1]);
    float4 v2 = __ldcg(&x[base + 2]);
    float4 v3 = __ldcg(&x[base + 3]);

    float lmin = fminf(fminf(v4min(v0), v4min(v1)), fminf(v4min(v2), v4min(v3)));
    float lmax = fmaxf(fmaxf(v4max(v0), v4max(v1)), fmaxf(v4max(v2), v4max(v3)));
    lmin = fminf(lmin, 0.0f);
    lmax = fmaxf(lmax, 0.0f);

    // Warp reduce via single-instruction REDUX on monotone-encoded uints.
    unsigned int emin = __reduce_min_sync(0xFFFFFFFFu, enc_f(lmin));
    unsigned int emax = __reduce_max_sync(0xFFFFFFFFu, enc_f(lmax));

    __shared__ unsigned int smin[8], smax[8];
    const int lane = threadIdx.x & 31;
    const int warp = threadIdx.x >> 5;
    if (lane == 0) { smin[warp] = emin; smax[warp] = emax; }
    __syncthreads();
    if (threadIdx.x < 8) {                       // lanes 0-7 of warp 0
        emin = __reduce_min_sync(0xFFu, smin[threadIdx.x]);
        emax = __reduce_max_sync(0xFFu, smax[threadIdx.x]);
        if (threadIdx.x == 0) {
            atomicMin(&g_min_enc, emin);
            atomicMax(&g_max_enc, emax);
        }
    }
}

// compare-exchange: u becomes max, v becomes min
#define SDP_CE(u, v) { float _hi = fmaxf(u, v), _lo = fminf(u, v); u = _hi; v = _lo; }

__device__ __forceinline__ void sdp_process_group(
    float4 va, float4 vb, float scale, float inv_scale,
    float4& oa, float4& ob)
{
    float xv[8]  = {va.x, va.y, va.z, va.w, vb.x, vb.y, vb.z, vb.w};
    float q[8];
    float mag[8];

    #pragma unroll
    for (int i = 0; i < 8; i++) {
        // Fast path: multiply by correctly-rounded reciprocal; differs from
        // the exact quotient by <=~1.5 ulp, which can only flip
        // round-half-to-even essentially on a .5 tie: detect that
        // neighborhood and redo with exact IEEE division (rare, ~0.2%).
        float y = xv[i] * inv_scale;
        float r = rintf(y);
        if (fabsf(fabsf(y - r) - 0.5f) < 1e-3f) {
            r = rintf(__fdiv_rn(xv[i], scale));
        }
        r = fminf(fmaxf(r, -128.0f), 127.0f);
        q[i]   = r;
        mag[i] = fabsf(r);   // integer-valued, 0..128
    }

    // 4th-largest of 8 via two sorted-4 runs + merge rank selection.
    float a0 = mag[0], a1 = mag[1], a2 = mag[2], a3 = mag[3];
    float b0 = mag[4], b1 = mag[5], b2 = mag[6], b3 = mag[7];
    SDP_CE(a0, a1); SDP_CE(a2, a3); SDP_CE(a0, a2); SDP_CE(a1, a3); SDP_CE(a1, a2);
    SDP_CE(b0, b1); SDP_CE(b2, b3); SDP_CE(b0, b2); SDP_CE(b1, b3); SDP_CE(b1, b2);
    float thr = fmaxf(fmaxf(a3, b3),
                      fmaxf(fminf(a0, b2), fmaxf(fminf(a1, b1), fminf(a2, b0))));

    #pragma unroll
    for (int i = 0; i < 8; i++) {
        // val = keep ? mag : floor(mag/16)*16  (all exact: small integers)
        const float tr16 = floorf(mag[i] * 0.0625f) * 16.0f;
        const float val  = (mag[i] >= thr) ? mag[i] : tr16;
        const float x_sdp = scale * copysignf(val, q[i]);
        xv[i] = xv[i] + (x_sdp - xv[i]);   // replicate reference rounding
    }

    oa = make_float4(xv[0], xv[1], xv[2], xv[3]);
    ob = make_float4(xv[4], xv[5], xv[6], xv[7]);
}

// One thread = two groups (16 elements, 4 LDG.128). Forward order, exact
// coverage grid. (R3-proven: 85.9us, 5.96 TB/s.)
__global__ void sdp_quant_kernel(const float4* __restrict__ x,
                                 float4* __restrict__ out) {
    const float r_min = dec_f(g_min_enc);
    const float r_max = dec_f(g_max_enc);
    const float scale = fmaxf(__fdiv_rn(r_max - r_min, 255.0f), 1e-8f);
    const float inv_scale = __frcp_rn(scale);

    const size_t base = ((size_t)blockIdx.x * blockDim.x + threadIdx.x) * 4;
    float4 v0 = __ldcs(&x[base + 0]);
    float4 v1 = __ldcs(&x[base + 1]);
    float4 v2 = __ldcs(&x[base + 2]);
    float4 v3 = __ldcs(&x[base + 3]);

    float4 o0, o1, o2, o3;
    sdp_process_group(v0, v1, scale, inv_scale, o0, o1);
    sdp_process_group(v2, v3, scale, inv_scale, o2, o3);

    __stcs(&out[base + 0], o0);
    __stcs(&out[base + 1], o1);
    __stcs(&out[base + 2], o2);
    __stcs(&out[base + 3], o3);
}

extern "C" void kernel_launch(void* const* d_in, const int* in_sizes, int n_in,
                              void* d_out, int out_size) {
    const float* x = (const float*)d_in[0];
    float* out = (float*)d_out;
    const int n = in_sizes[0];          // 67,108,864

    const int threads = 256;

    const int mm_blocks = n / (threads * 16);   // 16 elements per thread
    sdp_minmax_kernel<<<mm_blocks, threads>>>((const float4*)x);

    const int q_blocks = n / (threads * 16);    // 16 elements per thread
    sdp_quant_kernel<<<q_blocks, threads>>>((const float4*)x, (float4*)out);
}